// round 14
// baseline (speedup 1.0000x reference)
#include <cuda_runtime.h>
#include <cuda_fp16.h>
#include <cstdint>

#define TT 4096   // tokens = B*S
#define HH 1024   // hidden
#define FF 4096   // ffn
#define NE 8      // experts

#define BM 128
#define BN 128
#define BK 32
#define ASTAGES 4                   // A: cp.async pipeline depth
#define TILES_ME 8                  // m-tiles per expert (1024-token cap = 24 sigma)
#define A_STAGE_BYTES 8192          // 128 x 32 fp16
#define B_STAGE_BYTES 8192          // 32 k-rows x 128 n fp16 (256B rows)
#define SMEM_BYTES (ASTAGES * A_STAGE_BYTES + 2 * B_STAGE_BYTES + 256)

// ---------------- scratch (static device globals; no runtime alloc) --------
__device__ __half g_xg [(size_t)(TT + BM) * HH];  // gathered acts, fp16
__device__ __half g_mid[(size_t)(TT + BM) * FF];  // fc1 out (perm order), fp16
__device__ int    g_perm[TT];
__device__ int    g_expert_of[TT];
__device__ float  g_maxprob[TT];
__device__ int    g_cnt[NE];        // zero at load; router re-zeroes each run
__device__ int    g_off[NE + 1];
__device__ int    g_cur[NE];
__device__ int    g_done;           // router block completion counter

// ---------------- helpers ---------------------------------------------------
__device__ __forceinline__ uint32_t smem_u32(const void* p) {
    uint32_t a;
    asm("{ .reg .u64 t; cvta.to.shared.u64 t, %1; cvt.u32.u64 %0, t; }" : "=r"(a) : "l"(p));
    return a;
}
// pack two f32 -> f16x2 (first src -> HIGH half, second -> LOW half)
__device__ __forceinline__ uint32_t pack_f16x2(float hi, float lo) {
    uint32_t d;
    asm("cvt.rn.f16x2.f32 %0, %1, %2;" : "=r"(d) : "f"(hi), "f"(lo));
    return d;
}
__device__ __forceinline__ float gelu_exact(float v) {
    return 0.5f * v * (1.0f + erff(v * 0.7071067811865476f));
}
__device__ __forceinline__ void cp_async16(uint32_t dst, const void* src) {
    asm volatile("cp.async.cg.shared.global [%0], [%1], 16;" :: "r"(dst), "l"(src));
}
__device__ __forceinline__ void cp_commit() {
    asm volatile("cp.async.commit_group;" ::: "memory");
}
template<int N>
__device__ __forceinline__ void cp_wait() {
    asm volatile("cp.async.wait_group %0;" :: "n"(N) : "memory");
}

// ---------------- routing: router with fused scan ---------------------------
__global__ void router_kernel(const float* __restrict__ x,
                              const float* __restrict__ Wr,
                              const float* __restrict__ br) {
    int warp = (blockIdx.x * blockDim.x + threadIdx.x) >> 5;
    int lane = threadIdx.x & 31;
    const float* xr = x + (size_t)warp * HH;
    float acc[NE];
#pragma unroll
    for (int e = 0; e < NE; e++) acc[e] = 0.f;
    for (int i = lane; i < HH; i += 32) {
        float xv = xr[i];
        const float4* w4 = reinterpret_cast<const float4*>(Wr + i * NE);
        float4 w0 = w4[0], w1 = w4[1];
        acc[0] += xv * w0.x; acc[1] += xv * w0.y;
        acc[2] += xv * w0.z; acc[3] += xv * w0.w;
        acc[4] += xv * w1.x; acc[5] += xv * w1.y;
        acc[6] += xv * w1.z; acc[7] += xv * w1.w;
    }
#pragma unroll
    for (int e = 0; e < NE; e++) {
#pragma unroll
        for (int o = 16; o > 0; o >>= 1)
            acc[e] += __shfl_xor_sync(0xffffffffu, acc[e], o);
    }
    if (lane == 0) {
        float best = acc[0] + br[0]; int bi = 0;
#pragma unroll
        for (int e = 1; e < NE; e++) {
            float v = acc[e] + br[e];
            if (v > best) { best = v; bi = e; }
        }
        g_expert_of[warp] = bi;
        g_maxprob[warp]   = 1.0f / (1.0f + expf(-best));
        atomicAdd(&g_cnt[bi], 1);
    }
    // fused scan: last block to finish computes offsets + resets counters
    __syncthreads();
    if (threadIdx.x == 0) {
        __threadfence();
        int d = atomicAdd(&g_done, 1);
        if (d == (int)gridDim.x - 1) {
            int off = 0;
            for (int e = 0; e < NE; e++) {
                g_off[e] = off; g_cur[e] = off; off += g_cnt[e];
                g_cnt[e] = 0;                    // ready for next replay
            }
            g_off[NE] = off;
            g_done = 0;                          // ready for next replay
            __threadfence();
        }
    }
}

// fused: compute perm slot for this token AND gather its row to fp16
__global__ void permgather_kernel(const float* __restrict__ x) {
    __shared__ int s_slot;
    int tok = blockIdx.x;
    if (threadIdx.x == 0) {
        int e = g_expert_of[tok];
        int slot = atomicAdd(&g_cur[e], 1);
        g_perm[slot] = tok;
        s_slot = slot;
    }
    __syncthreads();
    int slot = s_slot;
    const float4* src = reinterpret_cast<const float4*>(x + (size_t)tok * HH);
    int c = threadIdx.x;            // 256 threads, 4 elems each
    float4 v = src[c];
    __half2 h0 = __floats2half2_rn(v.x, v.y);
    __half2 h1 = __floats2half2_rn(v.z, v.w);
    uint2 pk;
    pk.x = *reinterpret_cast<uint32_t*>(&h0);
    pk.y = *reinterpret_cast<uint32_t*>(&h1);
    *reinterpret_cast<uint2*>(g_xg + (size_t)slot * HH + 4 * c) = pk;
}

// ---------------- pipelined fp16 grouped GEMM (all-LDSM fragments) ----------
// FC1: g_mid = fp16( gelu( g_xg @ W1[e] ) )   K=HH, N over FF
// FC2: out   = ( g_mid @ W2[e] ) * p          K=FF, N over HH
//
// 256 threads, 8 warps (4 m x 2 n), warp tile 32x64, mma m16n8k16 f16.f16.f32.
// Per-thread-iter shared loads: 4 LDSM.x4 (A) + 8 LDSM.x4.trans (B)
// Smem A: fp16 [128][32], 64B rows, chunk16 ^ ((m>>1)&3), 4-stage cp.async.
// Smem B: fp16 [32 k][128 n], 256B rows, 16B-granule (n>>3) ^ (k&7) swizzle,
//         double-buffered LDG->cvt->STS; fragments via ldmatrix.trans.
template<int KTOT, bool FC2>
__global__ __launch_bounds__(256, 2)
void moe_gemm(const float* __restrict__ W, float* __restrict__ outp) {
    constexpr int LDB = FC2 ? HH : FF;
    constexpr int KIT = KTOT / BK;

    int e  = blockIdx.x >> 3;           // / TILES_ME
    int mt = blockIdx.x & 7;
    int off0 = g_off[e];
    int cnt  = g_off[e + 1] - off0;
    if (mt * BM >= cnt) return;
    int base = off0 + mt * BM;
    int n0   = blockIdx.y * BN;
    const float* Be = W + (size_t)e * KTOT * LDB;
    const __half* Abase = (FC2 ? g_mid : g_xg) + (size_t)base * KTOT;

    extern __shared__ char smem_raw[];
    uint32_t s_u32 = smem_u32(smem_raw);
    uint32_t s0    = (s_u32 + 127u) & ~127u;
    uint32_t sB0_u32 = s0 + ASTAGES * A_STAGE_BYTES;

    int tid = threadIdx.x, lane = tid & 31, wid = tid >> 5;
    int g = lane >> 2, t = lane & 3;
    int wm = wid >> 1, wn = wid & 1;
    int r0  = wm * 32;
    int nb0 = wn * 64;

    // ---- A ldmatrix per-lane constants ----
    int i8  = lane & 7;
    int qlo = (lane >> 3) & 1;
    int qhi = lane >> 4;
    uint32_t aoff = (uint32_t)(r0 + qlo * 8 + i8) * 64u;     // + mi*1024
    uint32_t s_a  = (uint32_t)((i8 >> 1) & 3);
    uint32_t Ta0  = ((uint32_t)qhi ^ s_a) << 4;              // ks=0 chunk
    uint32_t Ta1  = ((uint32_t)(2 + qhi) ^ s_a) << 4;        // ks=1 chunk

    // ---- B trans-ldmatrix per-lane constants ----
    // lane -> k row = ks*16 + (lane&15); n group = G + (lane>>4)
    uint32_t bfrag_base = (uint32_t)(lane & 15) * 256u;
    uint32_t bswz  = (uint32_t)(lane & 7);
    uint32_t gplus = (uint32_t)(lane >> 4);
    uint32_t Gbase = (uint32_t)(nb0 >> 3) + gplus;           // + 2*ni2

    // A loader: row am = tid>>1, chunks aj + {0,1}
    int am = tid >> 1;
    int aj = (tid & 1) * 2;
    const __half* Arow = Abase + (size_t)am * KTOT;
    uint32_t a_dst_base = s0 + (uint32_t)am * 64u;
    uint32_t a_sw = (uint32_t)((am >> 1) & 3);

    // B loader: thread handles k row = tid>>3, n segment (tid&7)*16
    int bk = tid >> 3;
    int nseg = tid & 7;
    const float* Bq = Be + (size_t)bk * LDB + n0 + nseg * 16;
    uint32_t bksw = (uint32_t)(bk & 7);
    uint32_t b_sts0 = (uint32_t)bk * 256u + ((((uint32_t)(2 * nseg))     ^ bksw) << 4);
    uint32_t b_sts1 = (uint32_t)bk * 256u + ((((uint32_t)(2 * nseg + 1)) ^ bksw) << 4);

    float acc[2][8][4];
#pragma unroll
    for (int mi = 0; mi < 2; mi++)
#pragma unroll
        for (int ni = 0; ni < 8; ni++)
#pragma unroll
            for (int c = 0; c < 4; c++) acc[mi][ni][c] = 0.f;

    uint32_t breg[8];

    auto issue_A = [&](int it) {
        uint32_t sb = (uint32_t)((it & (ASTAGES - 1)) * A_STAGE_BYTES);
        const __half* as = Arow + it * BK + aj * 8;
#pragma unroll
        for (int c = 0; c < 2; c++) {
            uint32_t ch = (uint32_t)(aj + c);
            cp_async16(a_dst_base + sb + ((ch ^ a_sw) << 4), as + c * 8);
        }
    };
    auto ldg_B = [&](int it) {
        const float* p = Bq + (size_t)(it * BK) * LDB;
        float4 v0 = *reinterpret_cast<const float4*>(p);
        float4 v1 = *reinterpret_cast<const float4*>(p + 4);
        float4 v2 = *reinterpret_cast<const float4*>(p + 8);
        float4 v3 = *reinterpret_cast<const float4*>(p + 12);
        breg[0] = pack_f16x2(v0.y, v0.x);   // n pairs (even -> low half)
        breg[1] = pack_f16x2(v0.w, v0.z);
        breg[2] = pack_f16x2(v1.y, v1.x);
        breg[3] = pack_f16x2(v1.w, v1.z);
        breg[4] = pack_f16x2(v2.y, v2.x);
        breg[5] = pack_f16x2(v2.w, v2.z);
        breg[6] = pack_f16x2(v3.y, v3.x);
        breg[7] = pack_f16x2(v3.w, v3.z);
    };
    auto sts_B = [&](int it) {
        uint32_t sb = sB0_u32 + (uint32_t)((it & 1) * B_STAGE_BYTES);
        asm volatile("st.shared.v4.b32 [%0], {%1,%2,%3,%4};" :: "r"(sb + b_sts0),
                     "r"(breg[0]), "r"(breg[1]), "r"(breg[2]), "r"(breg[3]));
        asm volatile("st.shared.v4.b32 [%0], {%1,%2,%3,%4};" :: "r"(sb + b_sts1),
                     "r"(breg[4]), "r"(breg[5]), "r"(breg[6]), "r"(breg[7]));
    };

    // prologue: A stages 0..2 via cp.async; B stage 0 STS'd, B stage 1 in regs
    issue_A(0); cp_commit();
    issue_A(1); cp_commit();
    issue_A(2); cp_commit();
    ldg_B(0);
    sts_B(0);
    ldg_B(1);

    for (int it = 0; it < KIT; it++) {
        cp_wait<ASTAGES - 2>();
        __syncthreads();
        if (it + 1 < KIT) sts_B(it + 1);
        if (it + 2 < KIT) ldg_B(it + 2);
        if (it + 3 < KIT) issue_A(it + 3);
        cp_commit();

        uint32_t sAu = s0 + (uint32_t)((it & (ASTAGES - 1)) * A_STAGE_BYTES);
        uint32_t sBu = sB0_u32 + (uint32_t)((it & 1) * B_STAGE_BYTES);

#pragma unroll
        for (int ks = 0; ks < 2; ks++) {          // two k16 steps per BK=32
            // ---- A fragments: one ldmatrix.x4 per (mi) ----
            uint32_t a[2][4];
            uint32_t Ta = ks ? Ta1 : Ta0;
#pragma unroll
            for (int mi = 0; mi < 2; mi++) {
                uint32_t addr = sAu + aoff + (uint32_t)(mi * 1024) + Ta;
                asm volatile(
                    "ldmatrix.sync.aligned.m8n8.x4.shared.b16 {%0,%1,%2,%3}, [%4];"
                    : "=r"(a[mi][0]), "=r"(a[mi][1]),
                      "=r"(a[mi][2]), "=r"(a[mi][3])
                    : "r"(addr));
            }
            // ---- B fragments: one ldmatrix.x4.trans per 2 ni ----
            // x4 = {m0: k0-7,Ggrp | m1: k8-15,Ggrp | m2: k0-7,Ggrp+1 | m3: k8-15,Ggrp+1}
            uint32_t b[8][2];
            uint32_t krow = sBu + (uint32_t)(ks * 4096) + bfrag_base;
#pragma unroll
            for (int ni2 = 0; ni2 < 4; ni2++) {
                uint32_t Ggrp = Gbase + (uint32_t)(2 * ni2);
                uint32_t addr = krow + ((Ggrp ^ bswz) << 4);
                asm volatile(
                    "ldmatrix.sync.aligned.m8n8.x4.trans.shared.b16 {%0,%1,%2,%3}, [%4];"
                    : "=r"(b[2 * ni2][0]),     "=r"(b[2 * ni2][1]),
                      "=r"(b[2 * ni2 + 1][0]), "=r"(b[2 * ni2 + 1][1])
                    : "r"(addr));
            }
#pragma unroll
            for (int mi = 0; mi < 2; mi++)
#pragma unroll
                for (int ni = 0; ni < 8; ni++) {
                    asm volatile(
                        "mma.sync.aligned.m16n8k16.row.col.f32.f16.f16.f32 "
                        "{%0,%1,%2,%3}, {%4,%5,%6,%7}, {%8,%9}, {%0,%1,%2,%3};\n"
                        : "+f"(acc[mi][ni][0]), "+f"(acc[mi][ni][1]),
                          "+f"(acc[mi][ni][2]), "+f"(acc[mi][ni][3])
                        : "r"(a[mi][0]), "r"(a[mi][1]), "r"(a[mi][2]), "r"(a[mi][3]),
                          "r"(b[ni][0]), "r"(b[ni][1]));
                }
        }
    }

    // ---------------- epilogue ----------------
#pragma unroll
    for (int mi = 0; mi < 2; mi++) {
#pragma unroll
        for (int half = 0; half < 2; half++) {
            int row = r0 + mi * 16 + half * 8 + g;
            if (mt * BM + row >= cnt) continue;
            if (!FC2) {
                __half* op = g_mid + (size_t)(base + row) * FF + n0;
#pragma unroll
                for (int ni = 0; ni < 8; ni++) {
                    __half2 hv = __floats2half2_rn(
                        gelu_exact(acc[mi][ni][half * 2 + 0]),
                        gelu_exact(acc[mi][ni][half * 2 + 1]));
                    *reinterpret_cast<__half2*>(op + nb0 + ni * 8 + 2 * t) = hv;
                }
            } else {
                int token = g_perm[base + row];
                float p = g_maxprob[token];
                float* op = outp + (size_t)token * HH + n0;
#pragma unroll
                for (int ni = 0; ni < 8; ni++) {
                    float2 v;
                    v.x = acc[mi][ni][half * 2 + 0] * p;
                    v.y = acc[mi][ni][half * 2 + 1] * p;
                    *reinterpret_cast<float2*>(op + nb0 + ni * 8 + 2 * t) = v;
                }
            }
        }
    }
}

// ---------------- launch ----------------------------------------------------
extern "C" void kernel_launch(void* const* d_in, const int* in_sizes, int n_in,
                              void* d_out, int out_size) {
    const float* x  = (const float*)d_in[0];
    const float* Wr = (const float*)d_in[1];
    const float* br = (const float*)d_in[2];
    const float* W1 = (const float*)d_in[3];
    const float* W2 = (const float*)d_in[4];
    float* out = (float*)d_out;

    cudaFuncSetAttribute(moe_gemm<HH, false>,
                         cudaFuncAttributeMaxDynamicSharedMemorySize, SMEM_BYTES);
    cudaFuncSetAttribute(moe_gemm<FF, true>,
                         cudaFuncAttributeMaxDynamicSharedMemorySize, SMEM_BYTES);

    router_kernel<<<TT / 8, 256>>>(x, Wr, br);          // scan fused (last block)
    permgather_kernel<<<TT, 256>>>(x);
    moe_gemm<HH, false><<<dim3(TILES_ME * NE, FF / BN), 256, SMEM_BYTES>>>(W1, nullptr);
    moe_gemm<FF, true ><<<dim3(TILES_ME * NE, HH / BN), 256, SMEM_BYTES>>>(W2, out);
}

// round 16
// speedup vs baseline: 1.1115x; 1.1115x over previous
#include <cuda_runtime.h>
#include <cuda_fp16.h>
#include <cstdint>

#define TT 4096   // tokens = B*S
#define HH 1024   // hidden
#define FF 4096   // ffn
#define NE 8      // experts

#define BM 128
#define BN 128
#define BK 32
#define ASTAGES 4                   // A: cp.async pipeline depth
#define TILES_ME 8                  // m-tiles per expert (1024-token cap = 24 sigma)
#define A_STAGE_BYTES 8192          // 128 x 32 fp16
#define B_STAGE_BYTES 8192          // 8 quad-rows x 64 pair-chunks x 16B
#define SMEM_BYTES (ASTAGES * A_STAGE_BYTES + 2 * B_STAGE_BYTES + 256)

// ---------------- scratch (static device globals; no runtime alloc) --------
__device__ __half g_xg [(size_t)(TT + BM) * HH];  // gathered acts, fp16
__device__ __half g_mid[(size_t)(TT + BM) * FF];  // fc1 out (perm order), fp16
__device__ int    g_perm[TT];
__device__ int    g_expert_of[TT];
__device__ float  g_maxprob[TT];
__device__ int    g_cnt[NE];        // zero at load; router re-zeroes each run
__device__ int    g_off[NE + 1];
__device__ int    g_cur[NE];
__device__ int    g_done;           // router block completion counter

// ---------------- helpers ---------------------------------------------------
__device__ __forceinline__ uint32_t smem_u32(const void* p) {
    uint32_t a;
    asm("{ .reg .u64 t; cvta.to.shared.u64 t, %1; cvt.u32.u64 %0, t; }" : "=r"(a) : "l"(p));
    return a;
}
// pack two f32 -> f16x2 (first src -> HIGH half, second -> LOW half)
__device__ __forceinline__ uint32_t pack_f16x2(float hi, float lo) {
    uint32_t d;
    asm("cvt.rn.f16x2.f32 %0, %1, %2;" : "=r"(d) : "f"(hi), "f"(lo));
    return d;
}
__device__ __forceinline__ float gelu_exact(float v) {
    return 0.5f * v * (1.0f + erff(v * 0.7071067811865476f));
}
__device__ __forceinline__ void cp_async16(uint32_t dst, const void* src) {
    asm volatile("cp.async.cg.shared.global [%0], [%1], 16;" :: "r"(dst), "l"(src));
}
__device__ __forceinline__ void cp_commit() {
    asm volatile("cp.async.commit_group;" ::: "memory");
}
template<int N>
__device__ __forceinline__ void cp_wait() {
    asm volatile("cp.async.wait_group %0;" :: "n"(N) : "memory");
}

// ---------------- routing: router with fused scan ---------------------------
__global__ void router_kernel(const float* __restrict__ x,
                              const float* __restrict__ Wr,
                              const float* __restrict__ br) {
    int warp = (blockIdx.x * blockDim.x + threadIdx.x) >> 5;
    int lane = threadIdx.x & 31;
    const float* xr = x + (size_t)warp * HH;
    float acc[NE];
#pragma unroll
    for (int e = 0; e < NE; e++) acc[e] = 0.f;
    for (int i = lane; i < HH; i += 32) {
        float xv = xr[i];
        const float4* w4 = reinterpret_cast<const float4*>(Wr + i * NE);
        float4 w0 = w4[0], w1 = w4[1];
        acc[0] += xv * w0.x; acc[1] += xv * w0.y;
        acc[2] += xv * w0.z; acc[3] += xv * w0.w;
        acc[4] += xv * w1.x; acc[5] += xv * w1.y;
        acc[6] += xv * w1.z; acc[7] += xv * w1.w;
    }
#pragma unroll
    for (int e = 0; e < NE; e++) {
#pragma unroll
        for (int o = 16; o > 0; o >>= 1)
            acc[e] += __shfl_xor_sync(0xffffffffu, acc[e], o);
    }
    if (lane == 0) {
        float best = acc[0] + br[0]; int bi = 0;
#pragma unroll
        for (int e = 1; e < NE; e++) {
            float v = acc[e] + br[e];
            if (v > best) { best = v; bi = e; }
        }
        g_expert_of[warp] = bi;
        g_maxprob[warp]   = 1.0f / (1.0f + expf(-best));
        atomicAdd(&g_cnt[bi], 1);
    }
    // fused scan: last block to finish computes offsets + resets counters
    __syncthreads();
    if (threadIdx.x == 0) {
        __threadfence();
        int d = atomicAdd(&g_done, 1);
        if (d == (int)gridDim.x - 1) {
            int off = 0;
            for (int e = 0; e < NE; e++) {
                g_off[e] = off; g_cur[e] = off; off += g_cnt[e];
                g_cnt[e] = 0;                    // ready for next replay
            }
            g_off[NE] = off;
            g_done = 0;                          // ready for next replay
            __threadfence();
        }
    }
}

// fused: compute perm slot for this token AND gather its row to fp16
__global__ void permgather_kernel(const float* __restrict__ x) {
    __shared__ int s_slot;
    int tok = blockIdx.x;
    if (threadIdx.x == 0) {
        int e = g_expert_of[tok];
        int slot = atomicAdd(&g_cur[e], 1);
        g_perm[slot] = tok;
        s_slot = slot;
    }
    __syncthreads();
    int slot = s_slot;
    const float4* src = reinterpret_cast<const float4*>(x + (size_t)tok * HH);
    int c = threadIdx.x;            // 256 threads, 4 elems each
    float4 v = src[c];
    __half2 h0 = __floats2half2_rn(v.x, v.y);
    __half2 h1 = __floats2half2_rn(v.z, v.w);
    uint2 pk;
    pk.x = *reinterpret_cast<uint32_t*>(&h0);
    pk.y = *reinterpret_cast<uint32_t*>(&h1);
    *reinterpret_cast<uint2*>(g_xg + (size_t)slot * HH + 4 * c) = pk;
}

// ---------------- pipelined fp16 grouped GEMM (LDSM A + paired LDS.128 B) ---
// FC1: g_mid = fp16( gelu( g_xg @ W1[e] ) )   K=HH, N over FF
// FC2: out   = ( g_mid @ W2[e] ) * p          K=FF, N over HH
//
// 256 threads, 8 warps (4 m x 2 n), warp tile 32x64, mma m16n8k16 f16.f16.f32.
// Per-thread-iter shared loads: 4 LDSM.x4 (A) + 8 LDS.128 (B)  [R13 had 20]
// Smem A: fp16 [128][32], 64B rows, chunk16 ^ ((m>>1)&3), 4-stage cp.async.
// Smem B: pair-packed [8 qr rows][64 chunks x 16B]; element (qr, n) 8B =
//         {h2(k,k+1), h2(k+8,k+9)} with k = 16*(qr>>2)+2*(qr&3);
//         chunk(g,q) holds n=16q+g (low 8B) and n+8 (high 8B) at
//         ch = (g ^ (2*(qr&3))) + 8q  — consumer LDS.128 conflict-free.
template<int KTOT, bool FC2>
__global__ __launch_bounds__(256, 2)
void moe_gemm(const float* __restrict__ W, float* __restrict__ outp) {
    constexpr int LDB = FC2 ? HH : FF;
    constexpr int KIT = KTOT / BK;

    int e  = blockIdx.x >> 3;           // / TILES_ME
    int mt = blockIdx.x & 7;
    int off0 = g_off[e];
    int cnt  = g_off[e + 1] - off0;
    if (mt * BM >= cnt) return;
    int base = off0 + mt * BM;
    int n0   = blockIdx.y * BN;
    const float* Be = W + (size_t)e * KTOT * LDB;
    const __half* Abase = (FC2 ? g_mid : g_xg) + (size_t)base * KTOT;

    extern __shared__ char smem_raw[];
    uint32_t s_u32 = smem_u32(smem_raw);
    uint32_t s0    = (s_u32 + 127u) & ~127u;
    uint32_t sB0_u32 = s0 + ASTAGES * A_STAGE_BYTES;

    int tid = threadIdx.x, lane = tid & 31, wid = tid >> 5;
    int g = lane >> 2, t = lane & 3;
    int wm = wid >> 1, wn = wid & 1;
    int r0  = wm * 32;
    int nb0 = wn * 64;

    // ---- A ldmatrix per-lane constants ----
    int i8  = lane & 7;
    int qlo = (lane >> 3) & 1;
    int qhi = lane >> 4;
    uint32_t aoff = (uint32_t)(r0 + qlo * 8 + i8) * 64u;     // + mi*1024
    uint32_t s_a  = (uint32_t)((i8 >> 1) & 3);
    uint32_t Ta0  = ((uint32_t)qhi ^ s_a) << 4;              // ks=0 chunk
    uint32_t Ta1  = ((uint32_t)(2 + qhi) ^ s_a) << 4;        // ks=1 chunk

    // ---- B consumer per-lane constants ----
    // per ks: row qr = ks*4 + t; chunk ch = (g ^ 2t) + 8*(nb0/16 + j)
    uint32_t chb  = (uint32_t)(g ^ (2 * t)) << 4;            // byte offset
    uint32_t qoffb = (uint32_t)nb0 * 8u;                     // 128*(nb0/16)

    // A loader: row am = tid>>1, chunks aj + {0,1}
    int am = tid >> 1;
    int aj = (tid & 1) * 2;
    const __half* Arow = Abase + (size_t)am * KTOT;
    uint32_t a_dst_base = s0 + (uint32_t)am * 64u;
    uint32_t a_sw = (uint32_t)((am >> 1) & 3);

    // B loader: warp qrl handles quad-row qrl (k rows rB,rB+1,rB+8,rB+9),
    // lane nb covers n = 4nb .. 4nb+3.
    int qrl = wid;
    int nb  = lane;
    int rB  = 16 * (qrl >> 2) + 2 * (qrl & 3);
    const float* Bq = Be + (size_t)rB * LDB + n0 + 4 * nb;
    // STS addresses: element n=4nb+s -> pair(g=4(nb&1)+s, q=nb>>2),
    // byte 8*((nb>>1)&1) inside chunk ch = (g ^ 2*(qrl&3)) + 8q
    uint32_t g0  = (uint32_t)((nb & 1) * 4);
    uint32_t qb  = (uint32_t)(nb >> 2);
    uint32_t h8  = (uint32_t)(((nb >> 1) & 1) * 8);
    uint32_t c2  = (uint32_t)((qrl & 3) * 2);
    uint32_t b_sts_row = (uint32_t)qrl * 1024u;
    uint32_t b_sts[4];
#pragma unroll
    for (int s = 0; s < 4; s++)
        b_sts[s] = b_sts_row + ((((g0 + (uint32_t)s) ^ c2) + 8u * qb) << 4) + h8;

    float acc[2][8][4];
#pragma unroll
    for (int mi = 0; mi < 2; mi++)
#pragma unroll
        for (int ni = 0; ni < 8; ni++)
#pragma unroll
            for (int c = 0; c < 4; c++) acc[mi][ni][c] = 0.f;

    uint32_t breg[8];

    auto issue_A = [&](int it) {
        uint32_t sb = (uint32_t)((it & (ASTAGES - 1)) * A_STAGE_BYTES);
        const __half* as = Arow + it * BK + aj * 8;
#pragma unroll
        for (int c = 0; c < 2; c++) {
            uint32_t ch = (uint32_t)(aj + c);
            cp_async16(a_dst_base + sb + ((ch ^ a_sw) << 4), as + c * 8);
        }
    };
    auto ldg_B = [&](int it) {
        const float* p = Bq + (size_t)(it * BK) * LDB;
        float4 r0v = *reinterpret_cast<const float4*>(p);
        float4 r1v = *reinterpret_cast<const float4*>(p + LDB);
        float4 r8v = *reinterpret_cast<const float4*>(p + 8 * (size_t)LDB);
        float4 r9v = *reinterpret_cast<const float4*>(p + 9 * (size_t)LDB);
        breg[0] = pack_f16x2(r1v.x, r0v.x);   // elem s=0: h2(k,k+1)
        breg[1] = pack_f16x2(r9v.x, r8v.x);   //          h2(k+8,k+9)
        breg[2] = pack_f16x2(r1v.y, r0v.y);
        breg[3] = pack_f16x2(r9v.y, r8v.y);
        breg[4] = pack_f16x2(r1v.z, r0v.z);
        breg[5] = pack_f16x2(r9v.z, r8v.z);
        breg[6] = pack_f16x2(r1v.w, r0v.w);
        breg[7] = pack_f16x2(r9v.w, r8v.w);
    };
    auto sts_B = [&](int it) {
        uint32_t sb = sB0_u32 + (uint32_t)((it & 1) * B_STAGE_BYTES);
        asm volatile("st.shared.v2.b32 [%0], {%1,%2};" :: "r"(sb + b_sts[0]),
                     "r"(breg[0]), "r"(breg[1]));
        asm volatile("st.shared.v2.b32 [%0], {%1,%2};" :: "r"(sb + b_sts[1]),
                     "r"(breg[2]), "r"(breg[3]));
        asm volatile("st.shared.v2.b32 [%0], {%1,%2};" :: "r"(sb + b_sts[2]),
                     "r"(breg[4]), "r"(breg[5]));
        asm volatile("st.shared.v2.b32 [%0], {%1,%2};" :: "r"(sb + b_sts[3]),
                     "r"(breg[6]), "r"(breg[7]));
    };

    // prologue: A stages 0..2 via cp.async; B stage 0 STS'd, B stage 1 in regs
    issue_A(0); cp_commit();
    issue_A(1); cp_commit();
    issue_A(2); cp_commit();
    ldg_B(0);
    sts_B(0);
    ldg_B(1);

    for (int it = 0; it < KIT; it++) {
        cp_wait<ASTAGES - 2>();
        __syncthreads();
        if (it + 1 < KIT) sts_B(it + 1);
        if (it + 2 < KIT) ldg_B(it + 2);
        if (it + 3 < KIT) issue_A(it + 3);
        cp_commit();

        uint32_t sAu = s0 + (uint32_t)((it & (ASTAGES - 1)) * A_STAGE_BYTES);
        uint32_t sBu = sB0_u32 + (uint32_t)((it & 1) * B_STAGE_BYTES);

#pragma unroll
        for (int ks = 0; ks < 2; ks++) {          // two k16 steps per BK=32
            // ---- A fragments: one ldmatrix.x4 per (mi) ----
            uint32_t a[2][4];
            uint32_t Ta = ks ? Ta1 : Ta0;
#pragma unroll
            for (int mi = 0; mi < 2; mi++) {
                uint32_t addr = sAu + aoff + (uint32_t)(mi * 1024) + Ta;
                asm volatile(
                    "ldmatrix.sync.aligned.m8n8.x4.shared.b16 {%0,%1,%2,%3}, [%4];"
                    : "=r"(a[mi][0]), "=r"(a[mi][1]),
                      "=r"(a[mi][2]), "=r"(a[mi][3])
                    : "r"(addr));
            }
            // ---- B fragments: one LDS.128 per ni-pair (pair-packed) ----
            uint32_t b[8][2];
            uint32_t rowb = sBu + (uint32_t)((ks * 4 + t) * 1024) + chb + qoffb;
#pragma unroll
            for (int j = 0; j < 4; j++) {
                uint32_t addr = rowb + (uint32_t)(128 * j);
                asm volatile("ld.shared.v4.b32 {%0,%1,%2,%3}, [%4];"
                             : "=r"(b[2 * j][0]), "=r"(b[2 * j][1]),
                               "=r"(b[2 * j + 1][0]), "=r"(b[2 * j + 1][1])
                             : "r"(addr));
            }
#pragma unroll
            for (int mi = 0; mi < 2; mi++)
#pragma unroll
                for (int ni = 0; ni < 8; ni++) {
                    asm volatile(
                        "mma.sync.aligned.m16n8k16.row.col.f32.f16.f16.f32 "
                        "{%0,%1,%2,%3}, {%4,%5,%6,%7}, {%8,%9}, {%0,%1,%2,%3};\n"
                        : "+f"(acc[mi][ni][0]), "+f"(acc[mi][ni][1]),
                          "+f"(acc[mi][ni][2]), "+f"(acc[mi][ni][3])
                        : "r"(a[mi][0]), "r"(a[mi][1]), "r"(a[mi][2]), "r"(a[mi][3]),
                          "r"(b[ni][0]), "r"(b[ni][1]));
                }
        }
    }

    // ---------------- epilogue ----------------
#pragma unroll
    for (int mi = 0; mi < 2; mi++) {
#pragma unroll
        for (int half = 0; half < 2; half++) {
            int row = r0 + mi * 16 + half * 8 + g;
            if (mt * BM + row >= cnt) continue;
            if (!FC2) {
                __half* op = g_mid + (size_t)(base + row) * FF + n0;
#pragma unroll
                for (int ni = 0; ni < 8; ni++) {
                    __half2 hv = __floats2half2_rn(
                        gelu_exact(acc[mi][ni][half * 2 + 0]),
                        gelu_exact(acc[mi][ni][half * 2 + 1]));
                    *reinterpret_cast<__half2*>(op + nb0 + ni * 8 + 2 * t) = hv;
                }
            } else {
                int token = g_perm[base + row];
                float p = g_maxprob[token];
                float* op = outp + (size_t)token * HH + n0;
#pragma unroll
                for (int ni = 0; ni < 8; ni++) {
                    float2 v;
                    v.x = acc[mi][ni][half * 2 + 0] * p;
                    v.y = acc[mi][ni][half * 2 + 1] * p;
                    *reinterpret_cast<float2*>(op + nb0 + ni * 8 + 2 * t) = v;
                }
            }
        }
    }
}

// ---------------- launch ----------------------------------------------------
extern "C" void kernel_launch(void* const* d_in, const int* in_sizes, int n_in,
                              void* d_out, int out_size) {
    const float* x  = (const float*)d_in[0];
    const float* Wr = (const float*)d_in[1];
    const float* br = (const float*)d_in[2];
    const float* W1 = (const float*)d_in[3];
    const float* W2 = (const float*)d_in[4];
    float* out = (float*)d_out;

    cudaFuncSetAttribute(moe_gemm<HH, false>,
                         cudaFuncAttributeMaxDynamicSharedMemorySize, SMEM_BYTES);
    cudaFuncSetAttribute(moe_gemm<FF, true>,
                         cudaFuncAttributeMaxDynamicSharedMemorySize, SMEM_BYTES);

    router_kernel<<<TT / 8, 256>>>(x, Wr, br);          // scan fused (last block)
    permgather_kernel<<<TT, 256>>>(x);
    moe_gemm<HH, false><<<dim3(TILES_ME * NE, FF / BN), 256, SMEM_BYTES>>>(W1, nullptr);
    moe_gemm<FF, true ><<<dim3(TILES_ME * NE, HH / BN), 256, SMEM_BYTES>>>(W2, out);
}

// round 17
// speedup vs baseline: 1.1496x; 1.0343x over previous
#include <cuda_runtime.h>
#include <cuda_fp16.h>
#include <cstdint>

#define TT 4096   // tokens = B*S
#define HH 1024   // hidden
#define FF 4096   // ffn
#define NE 8      // experts

#define BM 128
#define BN 128
#define BK 32
#define ASTAGES 4                   // A: cp.async pipeline depth
#define TILES_ME 8                  // m-tiles per expert (1024-token cap = 24 sigma)
#define EREG 1024                   // fixed region rows per expert
#define A_STAGE_BYTES 8192          // 128 x 32 fp16
#define B_STAGE_BYTES 8192          // 8 quad-rows x 128 n x 8B
#define SMEM_BYTES (ASTAGES * A_STAGE_BYTES + 2 * B_STAGE_BYTES + 256)
#define PG_TOK 32                   // tokens per permgather block

// ---------------- scratch (static device globals; no runtime alloc) --------
__device__ __half g_xg [(size_t)(NE * EREG + BM) * HH];  // gathered acts, fp16
__device__ __half g_mid[(size_t)(NE * EREG + BM) * FF];  // fc1 out (region order)
__device__ int    g_perm[NE * EREG];
__device__ int    g_expert_of[TT];
__device__ float  g_maxprob[TT];
__device__ int    g_cur[NE];        // slot cursors; router last block resets to e*EREG
__device__ int    g_done;           // router block completion counter

// ---------------- helpers ---------------------------------------------------
__device__ __forceinline__ uint32_t smem_u32(const void* p) {
    uint32_t a;
    asm("{ .reg .u64 t; cvta.to.shared.u64 t, %1; cvt.u32.u64 %0, t; }" : "=r"(a) : "l"(p));
    return a;
}
// pack two f32 -> f16x2 (first src -> HIGH half, second -> LOW half)
__device__ __forceinline__ uint32_t pack_f16x2(float hi, float lo) {
    uint32_t d;
    asm("cvt.rn.f16x2.f32 %0, %1, %2;" : "=r"(d) : "f"(hi), "f"(lo));
    return d;
}
__device__ __forceinline__ float gelu_exact(float v) {
    return 0.5f * v * (1.0f + erff(v * 0.7071067811865476f));
}
__device__ __forceinline__ void cp_async16(uint32_t dst, const void* src) {
    asm volatile("cp.async.cg.shared.global [%0], [%1], 16;" :: "r"(dst), "l"(src));
}
__device__ __forceinline__ void cp_commit() {
    asm volatile("cp.async.commit_group;" ::: "memory");
}
template<int N>
__device__ __forceinline__ void cp_wait() {
    asm volatile("cp.async.wait_group %0;" :: "n"(N) : "memory");
}

// ---------------- router: pure compute, no global atomics -------------------
__global__ void router_kernel(const float* __restrict__ x,
                              const float* __restrict__ Wr,
                              const float* __restrict__ br) {
    int warp = (blockIdx.x * blockDim.x + threadIdx.x) >> 5;
    int lane = threadIdx.x & 31;
    const float* xr = x + (size_t)warp * HH;
    float acc[NE];
#pragma unroll
    for (int e = 0; e < NE; e++) acc[e] = 0.f;
    for (int i = lane; i < HH; i += 32) {
        float xv = xr[i];
        const float4* w4 = reinterpret_cast<const float4*>(Wr + i * NE);
        float4 w0 = w4[0], w1 = w4[1];
        acc[0] += xv * w0.x; acc[1] += xv * w0.y;
        acc[2] += xv * w0.z; acc[3] += xv * w0.w;
        acc[4] += xv * w1.x; acc[5] += xv * w1.y;
        acc[6] += xv * w1.z; acc[7] += xv * w1.w;
    }
#pragma unroll
    for (int e = 0; e < NE; e++) {
#pragma unroll
        for (int o = 16; o > 0; o >>= 1)
            acc[e] += __shfl_xor_sync(0xffffffffu, acc[e], o);
    }
    if (lane == 0) {
        float best = acc[0] + br[0]; int bi = 0;
#pragma unroll
        for (int e = 1; e < NE; e++) {
            float v = acc[e] + br[e];
            if (v > best) { best = v; bi = e; }
        }
        g_expert_of[warp] = bi;
        g_maxprob[warp]   = 1.0f / (1.0f + expf(-best));
    }
    // last block resets slot cursors for the (up)coming permgather
    __syncthreads();
    if (threadIdx.x == 0) {
        __threadfence();
        int d = atomicAdd(&g_done, 1);
        if (d == (int)gridDim.x - 1) {
            for (int e = 0; e < NE; e++) g_cur[e] = e * EREG;
            g_done = 0;
            __threadfence();
        }
    }
}

// block-aggregated slot reservation + gather to fp16 (32 tokens per block)
__global__ void permgather_kernel(const float* __restrict__ x) {
    __shared__ int s_hist[NE], s_base[NE];
    __shared__ int s_exp[PG_TOK], s_rank[PG_TOK], s_slot[PG_TOK];
    int tid = threadIdx.x;
    int t0  = blockIdx.x * PG_TOK;
    if (tid < NE) s_hist[tid] = 0;
    __syncthreads();
    if (tid < PG_TOK) {
        int e = g_expert_of[t0 + tid];
        s_exp[tid]  = e;
        s_rank[tid] = atomicAdd(&s_hist[e], 1);
    }
    __syncthreads();
    if (tid < NE && s_hist[tid] > 0)
        s_base[tid] = atomicAdd(&g_cur[tid], s_hist[tid]);
    __syncthreads();
    if (tid < PG_TOK) {
        int slot = s_base[s_exp[tid]] + s_rank[tid];
        s_slot[tid] = slot;
        g_perm[slot] = t0 + tid;
    }
    __syncthreads();
    // copy: 8 threads per row, each thread 128 halfs (32 float4)
    int row = tid >> 3, seg = tid & 7;
    int tok  = t0 + row;
    int slot = s_slot[row];
    const float4* src = reinterpret_cast<const float4*>(x + (size_t)tok * HH + seg * 128);
    uint2* dst = reinterpret_cast<uint2*>(g_xg + (size_t)slot * HH + seg * 128);
#pragma unroll 4
    for (int i = 0; i < 32; i++) {
        float4 v = src[i];
        __half2 h0 = __floats2half2_rn(v.x, v.y);
        __half2 h1 = __floats2half2_rn(v.z, v.w);
        uint2 pk;
        pk.x = *reinterpret_cast<uint32_t*>(&h0);
        pk.y = *reinterpret_cast<uint32_t*>(&h1);
        dst[i] = pk;
    }
}

// ---------------- pipelined fp16 grouped GEMM (R13 core, fixed regions) -----
// FC1: g_mid = fp16( gelu( g_xg @ W1[e] ) )   K=HH, N over FF
// FC2: out   = ( g_mid @ W2[e] ) * p          K=FF, N over HH
//
// 256 threads, 8 warps (4 m x 2 n), warp tile 32x64, mma m16n8k16 f16.f16.f32.
// Per-thread-iter shared loads: 4 LDSM.x4 (A) + 16 LDS.64 (B) — best measured.
// Smem A: fp16 [128][32], 64B rows, chunk16 ^ ((m>>1)&3), 4-stage cp.async.
// Smem B: quad-packed [8 qr][128 n] 8B elems {h2(k,k+1), h2(k+8,k+9)},
//         element col n ^ (4*qr) swizzle, double-buffered LDG->cvt->STS.
template<int KTOT, bool FC2>
__global__ __launch_bounds__(256, 2)
void moe_gemm(const float* __restrict__ W, float* __restrict__ outp) {
    constexpr int LDB = FC2 ? HH : FF;
    constexpr int KIT = KTOT / BK;

    int e  = blockIdx.x >> 3;           // / TILES_ME
    int mt = blockIdx.x & 7;
    int off0 = e * EREG;
    int cnt  = g_cur[e] - off0;
    if (cnt > EREG) cnt = EREG;
    if (mt * BM >= cnt) return;
    int base = off0 + mt * BM;
    int n0   = blockIdx.y * BN;
    const float* Be = W + (size_t)e * KTOT * LDB;
    const __half* Abase = (FC2 ? g_mid : g_xg) + (size_t)base * KTOT;

    extern __shared__ char smem_raw[];
    uint32_t s_u32 = smem_u32(smem_raw);
    uint32_t s0    = (s_u32 + 127u) & ~127u;
    uint32_t sB0_u32 = s0 + ASTAGES * A_STAGE_BYTES;

    int tid = threadIdx.x, lane = tid & 31, wid = tid >> 5;
    int g = lane >> 2, t = lane & 3;
    int wm = wid >> 1, wn = wid & 1;
    int r0  = wm * 32;
    int nb0 = wn * 64;

    // ---- A ldmatrix per-lane constants ----
    int i8  = lane & 7;
    int qlo = (lane >> 3) & 1;
    int qhi = lane >> 4;
    uint32_t aoff = (uint32_t)(r0 + qlo * 8 + i8) * 64u;     // + mi*1024
    uint32_t s_a  = (uint32_t)((i8 >> 1) & 3);
    uint32_t Ta0  = ((uint32_t)qhi ^ s_a) << 4;              // ks=0 chunk
    uint32_t Ta1  = ((uint32_t)(2 + qhi) ^ s_a) << 4;        // ks=1 chunk

    // A loader: row am = tid>>1, chunks aj + {0,1}
    int am = tid >> 1;
    int aj = (tid & 1) * 2;
    const __half* Arow = Abase + (size_t)am * KTOT;
    uint32_t a_dst_base = s0 + (uint32_t)am * 64u;
    uint32_t a_sw = (uint32_t)((am >> 1) & 3);

    // B loader: warp qrl handles quad-row qrl (k rows rB, rB+1, rB+8, rB+9),
    // lane nb covers 4 n columns.
    int qrl = wid;
    int nb  = lane;
    int rB  = 16 * (qrl >> 2) + 2 * (qrl & 3);
    const float* Bq = Be + (size_t)rB * LDB + n0 + 4 * nb;
    uint32_t b_sts_base = (uint32_t)(qrl * 1024 + ((nb ^ qrl) * 32));

    float acc[2][8][4];
#pragma unroll
    for (int mi = 0; mi < 2; mi++)
#pragma unroll
        for (int ni = 0; ni < 8; ni++)
#pragma unroll
            for (int c = 0; c < 4; c++) acc[mi][ni][c] = 0.f;

    uint32_t breg[8];

    auto issue_A = [&](int it) {
        uint32_t sb = (uint32_t)((it & (ASTAGES - 1)) * A_STAGE_BYTES);
        const __half* as = Arow + it * BK + aj * 8;
#pragma unroll
        for (int c = 0; c < 2; c++) {
            uint32_t ch = (uint32_t)(aj + c);
            cp_async16(a_dst_base + sb + ((ch ^ a_sw) << 4), as + c * 8);
        }
    };
    auto ldg_B = [&](int it) {
        const float* p = Bq + (size_t)(it * BK) * LDB;
        float4 r0v = *reinterpret_cast<const float4*>(p);
        float4 r1v = *reinterpret_cast<const float4*>(p + LDB);
        float4 r8v = *reinterpret_cast<const float4*>(p + 8 * (size_t)LDB);
        float4 r9v = *reinterpret_cast<const float4*>(p + 9 * (size_t)LDB);
        breg[0] = pack_f16x2(r1v.x, r0v.x);   // elem j=0: h2(k,k+1)
        breg[1] = pack_f16x2(r9v.x, r8v.x);   //          h2(k+8,k+9)
        breg[2] = pack_f16x2(r1v.y, r0v.y);
        breg[3] = pack_f16x2(r9v.y, r8v.y);
        breg[4] = pack_f16x2(r1v.z, r0v.z);
        breg[5] = pack_f16x2(r9v.z, r8v.z);
        breg[6] = pack_f16x2(r1v.w, r0v.w);
        breg[7] = pack_f16x2(r9v.w, r8v.w);
    };
    auto sts_B = [&](int it) {
        uint32_t sb = sB0_u32 + (uint32_t)((it & 1) * B_STAGE_BYTES) + b_sts_base;
        asm volatile("st.shared.v4.b32 [%0], {%1,%2,%3,%4};" :: "r"(sb),
                     "r"(breg[0]), "r"(breg[1]), "r"(breg[2]), "r"(breg[3]));
        asm volatile("st.shared.v4.b32 [%0], {%1,%2,%3,%4};" :: "r"(sb + 16),
                     "r"(breg[4]), "r"(breg[5]), "r"(breg[6]), "r"(breg[7]));
    };

    // prologue: A stages 0..2 via cp.async; B stage 0 STS'd, B stage 1 in regs
    issue_A(0); cp_commit();
    issue_A(1); cp_commit();
    issue_A(2); cp_commit();
    ldg_B(0);
    sts_B(0);
    ldg_B(1);

    for (int it = 0; it < KIT; it++) {
        cp_wait<ASTAGES - 2>();
        __syncthreads();
        if (it + 1 < KIT) sts_B(it + 1);
        if (it + 2 < KIT) ldg_B(it + 2);
        if (it + 3 < KIT) issue_A(it + 3);
        cp_commit();

        uint32_t sAu = s0 + (uint32_t)((it & (ASTAGES - 1)) * A_STAGE_BYTES);
        uint32_t sBu = sB0_u32 + (uint32_t)((it & 1) * B_STAGE_BYTES);

#pragma unroll
        for (int ks = 0; ks < 2; ks++) {          // two k16 steps per BK=32
            // ---- A fragments: one ldmatrix.x4 per (mi) ----
            uint32_t a[2][4];
            uint32_t Ta = ks ? Ta1 : Ta0;
#pragma unroll
            for (int mi = 0; mi < 2; mi++) {
                uint32_t addr = sAu + aoff + (uint32_t)(mi * 1024) + Ta;
                asm volatile(
                    "ldmatrix.sync.aligned.m8n8.x4.shared.b16 {%0,%1,%2,%3}, [%4];"
                    : "=r"(a[mi][0]), "=r"(a[mi][1]),
                      "=r"(a[mi][2]), "=r"(a[mi][3])
                    : "r"(addr));
            }
            // ---- B fragments: one LDS.64 per ni (quad-packed) ----
            uint32_t b[8][2];
            uint32_t qr   = (uint32_t)(ks * 4 + t);
            uint32_t rowb = sBu + qr * 1024u;
            uint32_t fq   = qr * 4u;
#pragma unroll
            for (int ni = 0; ni < 8; ni++) {
                uint32_t n = (uint32_t)(nb0 + ni * 8 + g);
                uint32_t addr = rowb + ((n ^ fq) << 3);
                asm volatile("ld.shared.v2.b32 {%0,%1}, [%2];"
                             : "=r"(b[ni][0]), "=r"(b[ni][1]) : "r"(addr));
            }
#pragma unroll
            for (int mi = 0; mi < 2; mi++)
#pragma unroll
                for (int ni = 0; ni < 8; ni++) {
                    asm volatile(
                        "mma.sync.aligned.m16n8k16.row.col.f32.f16.f16.f32 "
                        "{%0,%1,%2,%3}, {%4,%5,%6,%7}, {%8,%9}, {%0,%1,%2,%3};\n"
                        : "+f"(acc[mi][ni][0]), "+f"(acc[mi][ni][1]),
                          "+f"(acc[mi][ni][2]), "+f"(acc[mi][ni][3])
                        : "r"(a[mi][0]), "r"(a[mi][1]), "r"(a[mi][2]), "r"(a[mi][3]),
                          "r"(b[ni][0]), "r"(b[ni][1]));
                }
        }
    }

    // ---------------- epilogue ----------------
#pragma unroll
    for (int mi = 0; mi < 2; mi++) {
#pragma unroll
        for (int half = 0; half < 2; half++) {
            int row = r0 + mi * 16 + half * 8 + g;
            if (mt * BM + row >= cnt) continue;
            if (!FC2) {
                __half* op = g_mid + (size_t)(base + row) * FF + n0;
#pragma unroll
                for (int ni = 0; ni < 8; ni++) {
                    __half2 hv = __floats2half2_rn(
                        gelu_exact(acc[mi][ni][half * 2 + 0]),
                        gelu_exact(acc[mi][ni][half * 2 + 1]));
                    *reinterpret_cast<__half2*>(op + nb0 + ni * 8 + 2 * t) = hv;
                }
            } else {
                int token = g_perm[base + row];
                float p = g_maxprob[token];
                float* op = outp + (size_t)token * HH + n0;
#pragma unroll
                for (int ni = 0; ni < 8; ni++) {
                    float2 v;
                    v.x = acc[mi][ni][half * 2 + 0] * p;
                    v.y = acc[mi][ni][half * 2 + 1] * p;
                    *reinterpret_cast<float2*>(op + nb0 + ni * 8 + 2 * t) = v;
                }
            }
        }
    }
}

// ---------------- launch ----------------------------------------------------
extern "C" void kernel_launch(void* const* d_in, const int* in_sizes, int n_in,
                              void* d_out, int out_size) {
    const float* x  = (const float*)d_in[0];
    const float* Wr = (const float*)d_in[1];
    const float* br = (const float*)d_in[2];
    const float* W1 = (const float*)d_in[3];
    const float* W2 = (const float*)d_in[4];
    float* out = (float*)d_out;

    cudaFuncSetAttribute(moe_gemm<HH, false>,
                         cudaFuncAttributeMaxDynamicSharedMemorySize, SMEM_BYTES);
    cudaFuncSetAttribute(moe_gemm<FF, true>,
                         cudaFuncAttributeMaxDynamicSharedMemorySize, SMEM_BYTES);

    router_kernel<<<TT / 8, 256>>>(x, Wr, br);      // cursor reset in last block
    permgather_kernel<<<TT / PG_TOK, 256>>>(x);     // aggregated reservations
    moe_gemm<HH, false><<<dim3(TILES_ME * NE, FF / BN), 256, SMEM_BYTES>>>(W1, nullptr);
    moe_gemm<FF, true ><<<dim3(TILES_ME * NE, HH / BN), 256, SMEM_BYTES>>>(W2, out);
}